// round 7
// baseline (speedup 1.0000x reference)
#include <cuda_runtime.h>
#include <cstdint>

// Problem dims (fixed by the reference)
#define T_STEPS 512
#define BATCH   256
#define DIN     128
#define DH      512
#define DOUT    128

// Persistent recurrence config: 8 row-blocks x 16 col-blocks of 32x32 tiles
#define NCTA        128
#define REC_THREADS 128

// -------------------- device scratch (no allocation allowed) --------------------
__device__ float    g_xproj[(size_t)T_STEPS * BATCH * DH];   // 256 MB
__device__ float    g_h[2][BATCH * DH];                      // ping-pong hidden state
__device__ unsigned g_bar[T_STEPS];                          // per-step barrier counters

// -------------------- reset (runs every replay: determinism) --------------------
__global__ void reset_kernel() {
    int idx    = blockIdx.x * blockDim.x + threadIdx.x;
    int stride = gridDim.x * blockDim.x;
    if (idx < T_STEPS) g_bar[idx] = 0u;
    for (int i = idx; i < BATCH * DH; i += stride) g_h[0][i] = 0.0f;
}

// -------------------- xproj = xs @ W1x  (M=131072, N=512, K=128) --------------------
// 64x64 tiles, 256 threads, 4x4 microtile. fp32, fully parallel.
#define XPROJ_SMEM_FLOATS (64 * 132 + 128 * 64)
__global__ void __launch_bounds__(256) xproj_kernel(const float* __restrict__ xs,
                                                    const float* __restrict__ W1x) {
    extern __shared__ float sm[];
    float* xs_sm = sm;              // [64][132] (pad 4 -> conflict-free a loads)
    float* w_sm  = sm + 64 * 132;   // [128][64]

    const int tid  = threadIdx.x;
    const int row0 = blockIdx.x * 64;   // over T*B = 131072 rows
    const int col0 = blockIdx.y * 64;   // over DH = 512 cols

    // Stage xs tile (64 x 128 floats)
#pragma unroll
    for (int i = 0; i < 8; i++) {
        int idx = tid + i * 256;
        int r = idx >> 5, c4 = idx & 31;
        float4 v = *reinterpret_cast<const float4*>(xs + (size_t)(row0 + r) * DIN + c4 * 4);
        *reinterpret_cast<float4*>(xs_sm + r * 132 + c4 * 4) = v;
    }
    // Stage W1x tile (128 x 64 floats)
#pragma unroll
    for (int i = 0; i < 8; i++) {
        int idx = tid + i * 256;
        int k = idx >> 4, j4 = idx & 15;
        float4 v = *reinterpret_cast<const float4*>(W1x + (size_t)k * DH + col0 + j4 * 4);
        *reinterpret_cast<float4*>(w_sm + k * 64 + j4 * 4) = v;
    }
    __syncthreads();

    const int tx = tid & 15;   // 16 col groups of 4
    const int ty = tid >> 4;   // 16 row groups of 4

    float acc[4][4];
#pragma unroll
    for (int i = 0; i < 4; i++)
#pragma unroll
        for (int j = 0; j < 4; j++) acc[i][j] = 0.0f;

    const float*  a0p = xs_sm + (ty * 4 + 0) * 132;
    const float*  a1p = xs_sm + (ty * 4 + 1) * 132;
    const float*  a2p = xs_sm + (ty * 4 + 2) * 132;
    const float*  a3p = xs_sm + (ty * 4 + 3) * 132;
    const float4* w4  = reinterpret_cast<const float4*>(w_sm);

#pragma unroll 8
    for (int k = 0; k < DIN; k++) {
        float  a0 = a0p[k], a1 = a1p[k], a2 = a2p[k], a3 = a3p[k];
        float4 w  = w4[k * 16 + tx];
        acc[0][0] += a0 * w.x; acc[0][1] += a0 * w.y; acc[0][2] += a0 * w.z; acc[0][3] += a0 * w.w;
        acc[1][0] += a1 * w.x; acc[1][1] += a1 * w.y; acc[1][2] += a1 * w.z; acc[1][3] += a1 * w.w;
        acc[2][0] += a2 * w.x; acc[2][1] += a2 * w.y; acc[2][2] += a2 * w.z; acc[2][3] += a2 * w.w;
        acc[3][0] += a3 * w.x; acc[3][1] += a3 * w.y; acc[3][2] += a3 * w.z; acc[3][3] += a3 * w.w;
    }

#pragma unroll
    for (int i = 0; i < 4; i++) {
        float4 o = make_float4(acc[i][0], acc[i][1], acc[i][2], acc[i][3]);
        *reinterpret_cast<float4*>(g_xproj + (size_t)(row0 + ty * 4 + i) * DH + col0 + tx * 4) = o;
    }
}

// -------------------- persistent recurrence --------------------
// 128 CTAs, one per 32x32 tile of h. W1h column block (512x32 = 64KB) SMEM-resident
// across all 512 steps. Per step: restage own 32 h-rows (L2 -> SMEM), GEMM, tanh,
// store, grid barrier.
#define REC_SMEM_FLOATS (DH * 32 + 32 * 516)
__global__ void __launch_bounds__(REC_THREADS, 1)
rec_kernel(const float* __restrict__ W1h, const float* __restrict__ b1p) {
    extern __shared__ float sm[];
    float* w_sm = sm;             // [512][32]
    float* h_sm = sm + DH * 32;   // [32][516]  (pad 4 -> conflict-free column reads)

    const int tid  = threadIdx.x;
    const int cb   = blockIdx.x & 15;   // 16 column blocks
    const int rb   = blockIdx.x >> 4;   // 8 row blocks
    const int col0 = cb * 32;
    const int row0 = rb * 32;
    const int tx   = tid & 7;           // 8 col groups of 4
    const int ty   = tid >> 3;          // 16 -> rows ty and ty+16

    // Prologue: load W1h[:, col0:col0+32] into SMEM, once.
#pragma unroll 8
    for (int i = 0; i < 32; i++) {
        int idx = tid + i * REC_THREADS;
        int k = idx >> 3, j4 = idx & 7;
        float4 v = *reinterpret_cast<const float4*>(W1h + (size_t)k * DH + col0 + j4 * 4);
        *reinterpret_cast<float4*>(w_sm + k * 32 + j4 * 4) = v;
    }
    const float bias = b1p[0];
    __syncthreads();

    const float*  hin   = g_h[0];
    float*        hout  = g_h[1];
    const float*  hr0   = h_sm + (size_t)ty * 516;
    const float*  hr1   = h_sm + (size_t)(ty + 16) * 516;
    const float4* w4    = reinterpret_cast<const float4*>(w_sm);

    for (int s = 0; s < T_STEPS; s++) {
        // Prefetch xproj init values (overlaps with h restage below)
        const float* xp = g_xproj + ((size_t)s * BATCH + row0) * DH + col0;
        float4 x0 = __ldcg(reinterpret_cast<const float4*>(xp + (size_t)ty * DH + tx * 4));
        float4 x1 = __ldcg(reinterpret_cast<const float4*>(xp + (size_t)(ty + 16) * DH + tx * 4));

        // Restage h tile (32 rows x 512) L2 -> SMEM. __ldcg: never serve stale L1.
#pragma unroll 8
        for (int i = 0; i < 32; i++) {
            int idx = tid + i * REC_THREADS;
            int r = idx >> 7, c4 = idx & 127;
            float4 v = __ldcg(reinterpret_cast<const float4*>(hin + (size_t)(row0 + r) * DH + c4 * 4));
            *reinterpret_cast<float4*>(h_sm + r * 516 + c4 * 4) = v;
        }
        __syncthreads();

        float a00 = x0.x + bias, a01 = x0.y + bias, a02 = x0.z + bias, a03 = x0.w + bias;
        float a10 = x1.x + bias, a11 = x1.y + bias, a12 = x1.z + bias, a13 = x1.w + bias;

#pragma unroll 8
        for (int k = 0; k < DH; k++) {
            float  h0 = hr0[k];
            float  h1 = hr1[k];
            float4 w  = w4[k * 8 + tx];
            a00 += h0 * w.x; a01 += h0 * w.y; a02 += h0 * w.z; a03 += h0 * w.w;
            a10 += h1 * w.x; a11 += h1 * w.y; a12 += h1 * w.z; a13 += h1 * w.w;
        }

        float4 o0 = make_float4(tanhf(a00), tanhf(a01), tanhf(a02), tanhf(a03));
        float4 o1 = make_float4(tanhf(a10), tanhf(a11), tanhf(a12), tanhf(a13));
        *reinterpret_cast<float4*>(hout + (size_t)(row0 + ty) * DH + col0 + tx * 4)      = o0;
        *reinterpret_cast<float4*>(hout + (size_t)(row0 + ty + 16) * DH + col0 + tx * 4) = o1;

        if (s < T_STEPS - 1) {
            __threadfence();            // release: publish hout before arrival
            __syncthreads();            // all threads of CTA released
            if (tid == 0) {
                atomicAdd(&g_bar[s], 1u);
                while (*((volatile unsigned*)&g_bar[s]) < (unsigned)NCTA) { }
            }
            __syncthreads();            // fan out barrier release within CTA
        }

        const float* tmp = hin; hin = hout; hout = const_cast<float*>(tmp);
    }
    // 512 steps (even): final h lives in g_h[0].
}

// -------------------- out = h_final @ W2 + b2 --------------------
__global__ void __launch_bounds__(128) out_kernel(const float* __restrict__ W2,
                                                  const float* __restrict__ b2p,
                                                  float* __restrict__ out) {
    __shared__ float hs[DH];
    const int b = blockIdx.x;
    const int o = threadIdx.x;
    for (int i = o; i < DH; i += 128) hs[i] = g_h[0][(size_t)b * DH + i];
    __syncthreads();
    float acc = b2p[0];
#pragma unroll 8
    for (int k = 0; k < DH; k++) acc += hs[k] * W2[(size_t)k * DOUT + o];
    out[(size_t)b * DOUT + o] = acc;
}

// -------------------- launch --------------------
extern "C" void kernel_launch(void* const* d_in, const int* in_sizes, int n_in,
                              void* d_out, int out_size) {
    const float* xs  = (const float*)d_in[0];
    const float* W1x = (const float*)d_in[1];
    const float* W1h = (const float*)d_in[2];
    const float* b1  = (const float*)d_in[3];
    const float* W2  = (const float*)d_in[4];
    const float* b2  = (const float*)d_in[5];
    float* out = (float*)d_out;

    (void)in_sizes; (void)n_in; (void)out_size;

    cudaFuncSetAttribute(xproj_kernel, cudaFuncAttributeMaxDynamicSharedMemorySize,
                         XPROJ_SMEM_FLOATS * (int)sizeof(float));
    cudaFuncSetAttribute(rec_kernel, cudaFuncAttributeMaxDynamicSharedMemorySize,
                         REC_SMEM_FLOATS * (int)sizeof(float));

    reset_kernel<<<128, 256>>>();
    xproj_kernel<<<dim3((T_STEPS * BATCH) / 64, DH / 64), 256,
                   XPROJ_SMEM_FLOATS * sizeof(float)>>>(xs, W1x);
    rec_kernel<<<NCTA, REC_THREADS, REC_SMEM_FLOATS * sizeof(float)>>>(W1h, b1);
    out_kernel<<<BATCH, 128>>>(W2, b2, out);
}

// round 8
// speedup vs baseline: 1.0810x; 1.0810x over previous
#include <cuda_runtime.h>
#include <cstdint>

// Problem dims (fixed by the reference)
#define T_STEPS 512
#define BATCH   256
#define DIN     128
#define DH      512
#define DOUT    128

// Persistent recurrence config: 8 row-blocks x 16 col-blocks of 32x32 tiles
#define NCTA        128
#define CBLK        16
#define REC_THREADS 128

typedef unsigned long long ull;

// -------------------- device scratch (no allocation allowed) --------------------
__device__ float    g_xproj[(size_t)T_STEPS * BATCH * DH];   // 256 MB
__device__ float    g_h[2][BATCH * DH];                      // ping-pong hidden state
__device__ unsigned g_flag[T_STEPS * NCTA];                  // per-(step,tile) ready flags

// -------------------- asm helpers --------------------
__device__ __forceinline__ ull fma2(ull a, ull b, ull c) {
    ull d;
    asm("fma.rn.f32x2 %0, %1, %2, %3;" : "=l"(d) : "l"(a), "l"(b), "l"(c));
    return d;
}
__device__ __forceinline__ float sum2(ull v) {
    float lo, hi;
    asm("mov.b64 {%0, %1}, %2;" : "=f"(lo), "=f"(hi) : "l"(v));
    return lo + hi;
}
__device__ __forceinline__ unsigned ld_acquire(const unsigned* p) {
    unsigned v;
    asm volatile("ld.acquire.gpu.global.u32 %0, [%1];" : "=r"(v) : "l"(p) : "memory");
    return v;
}
__device__ __forceinline__ void st_release(unsigned* p, unsigned v) {
    asm volatile("st.release.gpu.global.u32 [%0], %1;" :: "l"(p), "r"(v) : "memory");
}

// -------------------- reset (runs every replay: determinism) --------------------
// 256 blocks x 256 threads = 65536 threads: zero all flags + h0.
__global__ void reset_kernel() {
    int idx = blockIdx.x * blockDim.x + threadIdx.x;
    g_flag[idx] = 0u;
    g_h[0][idx * 2 + 0] = 0.0f;
    g_h[0][idx * 2 + 1] = 0.0f;
}

// -------------------- xproj = xs @ W1x  (M=131072, N=512, K=128) --------------------
// 64x64 tiles, 256 threads, 4x4 microtile. fp32, fully parallel. (Unchanged, known-good.)
#define XPROJ_SMEM_FLOATS (64 * 132 + 128 * 64)
__global__ void __launch_bounds__(256) xproj_kernel(const float* __restrict__ xs,
                                                    const float* __restrict__ W1x) {
    extern __shared__ float sm[];
    float* xs_sm = sm;              // [64][132]
    float* w_sm  = sm + 64 * 132;   // [128][64]

    const int tid  = threadIdx.x;
    const int row0 = blockIdx.x * 64;
    const int col0 = blockIdx.y * 64;

#pragma unroll
    for (int i = 0; i < 8; i++) {
        int idx = tid + i * 256;
        int r = idx >> 5, c4 = idx & 31;
        float4 v = *reinterpret_cast<const float4*>(xs + (size_t)(row0 + r) * DIN + c4 * 4);
        *reinterpret_cast<float4*>(xs_sm + r * 132 + c4 * 4) = v;
    }
#pragma unroll
    for (int i = 0; i < 8; i++) {
        int idx = tid + i * 256;
        int k = idx >> 4, j4 = idx & 15;
        float4 v = *reinterpret_cast<const float4*>(W1x + (size_t)k * DH + col0 + j4 * 4);
        *reinterpret_cast<float4*>(w_sm + k * 64 + j4 * 4) = v;
    }
    __syncthreads();

    const int tx = tid & 15;
    const int ty = tid >> 4;

    float acc[4][4];
#pragma unroll
    for (int i = 0; i < 4; i++)
#pragma unroll
        for (int j = 0; j < 4; j++) acc[i][j] = 0.0f;

    const float*  a0p = xs_sm + (ty * 4 + 0) * 132;
    const float*  a1p = xs_sm + (ty * 4 + 1) * 132;
    const float*  a2p = xs_sm + (ty * 4 + 2) * 132;
    const float*  a3p = xs_sm + (ty * 4 + 3) * 132;
    const float4* w4  = reinterpret_cast<const float4*>(w_sm);

#pragma unroll 8
    for (int k = 0; k < DIN; k++) {
        float  a0 = a0p[k], a1 = a1p[k], a2 = a2p[k], a3 = a3p[k];
        float4 w  = w4[k * 16 + tx];
        acc[0][0] += a0 * w.x; acc[0][1] += a0 * w.y; acc[0][2] += a0 * w.z; acc[0][3] += a0 * w.w;
        acc[1][0] += a1 * w.x; acc[1][1] += a1 * w.y; acc[1][2] += a1 * w.z; acc[1][3] += a1 * w.w;
        acc[2][0] += a2 * w.x; acc[2][1] += a2 * w.y; acc[2][2] += a2 * w.z; acc[2][3] += a2 * w.w;
        acc[3][0] += a3 * w.x; acc[3][1] += a3 * w.y; acc[3][2] += a3 * w.z; acc[3][3] += a3 * w.w;
    }

#pragma unroll
    for (int i = 0; i < 4; i++) {
        float4 o = make_float4(acc[i][0], acc[i][1], acc[i][2], acc[i][3]);
        *reinterpret_cast<float4*>(g_xproj + (size_t)(row0 + ty * 4 + i) * DH + col0 + tx * 4) = o;
    }
}

// -------------------- persistent recurrence --------------------
// 128 CTAs, one per 32x32 tile of h. W1h column block SMEM-resident, k-transposed with
// per-column shift 4*(c>>2) (conflict-free packed LDS). Packed fma.rn.f32x2 math.
// Row-local release/acquire flags replace the global barrier.
#define W_STRIDE  544                // 512 + 32(shift headroom); 544 % 32 == 0
#define H_STRIDE  520                // 512 + 8 pad; (8*ty) mod 32 spreads rows
#define REC_SMEM_FLOATS (32 * W_STRIDE + 32 * H_STRIDE)

__global__ void __launch_bounds__(REC_THREADS, 1)
rec_kernel(const float* __restrict__ W1h, const float* __restrict__ b1p) {
    extern __shared__ float sm[];
    float* w_smT = sm;                    // [32 cols][544], col c shifted by 4*(c>>2)
    float* h_sm  = sm + 32 * W_STRIDE;    // [32 rows][520]

    const int tid  = threadIdx.x;
    const int bid  = blockIdx.x;
    const int cb   = bid & 15;            // 16 column blocks
    const int rb   = bid >> 4;            // 8 row blocks
    const int col0 = cb * 32;
    const int row0 = rb * 32;
    const int tx   = tid & 7;             // 8 col groups of 4
    const int ty   = tid >> 3;            // rows ty and ty+16

    // Prologue: W1h[:, col0:col0+32] -> w_smT, k-transposed + shifted. Once.
    // 4096 float4 row-chunks; element (c,k) -> w_smT[c*544 + 4*(c>>2) + k].
#pragma unroll 4
    for (int i = 0; i < 32; i++) {
        int idx = i * REC_THREADS + tid;          // 0..4095
        int c4  = idx & 7;                        // float4 group within row
        int k   = idx >> 3;
        float4 v = *reinterpret_cast<const float4*>(W1h + (size_t)k * DH + col0 + c4 * 4);
        int shift = 4 * c4;                       // (c>>2) == c4 for all 4 elems
        w_smT[(c4 * 4 + 0) * W_STRIDE + shift + k] = v.x;
        w_smT[(c4 * 4 + 1) * W_STRIDE + shift + k] = v.y;
        w_smT[(c4 * 4 + 2) * W_STRIDE + shift + k] = v.z;
        w_smT[(c4 * 4 + 3) * W_STRIDE + shift + k] = v.w;
    }
    const float bias = b1p[0];
    __syncthreads();

    const float* hin  = g_h[0];
    float*       hout = g_h[1];

    const float* hr0 = h_sm + (size_t)ty * H_STRIDE;
    const float* hr1 = h_sm + (size_t)(ty + 16) * H_STRIDE;
    // Per-thread W column pointers (columns 4tx..4tx+3, shift 4tx each)
    const float* w0 = w_smT + (size_t)(4 * tx + 0) * W_STRIDE + 4 * tx;
    const float* w1 = w_smT + (size_t)(4 * tx + 1) * W_STRIDE + 4 * tx;
    const float* w2 = w_smT + (size_t)(4 * tx + 2) * W_STRIDE + 4 * tx;
    const float* w3 = w_smT + (size_t)(4 * tx + 3) * W_STRIDE + 4 * tx;

    for (int s = 0; s < T_STEPS; s++) {
        // Prefetch xproj (independent of flags -> hides L2/DRAM latency behind wait)
        const float* xp = g_xproj + ((size_t)s * BATCH + row0) * DH + col0;
        float4 x0 = __ldcg(reinterpret_cast<const float4*>(xp + (size_t)ty * DH + tx * 4));
        float4 x1 = __ldcg(reinterpret_cast<const float4*>(xp + (size_t)(ty + 16) * DH + tx * 4));

        // Wait for the 16 producer tiles of our row block (step s-1)
        if (s > 0) {
            if (tid < CBLK) {
                const unsigned* f = &g_flag[(s - 1) * NCTA + rb * CBLK + tid];
                while (ld_acquire(f) == 0u) { }
            }
            __syncthreads();
        }

        // Restage h tile (32 rows x 512) L2 -> SMEM. __ldcg: L1 is incoherent.
#pragma unroll 8
        for (int i = 0; i < 32; i++) {
            int idx = i * REC_THREADS + tid;
            int r = idx >> 7, c4 = idx & 127;
            float4 v = __ldcg(reinterpret_cast<const float4*>(hin + (size_t)(row0 + r) * DH + c4 * 4));
            *reinterpret_cast<float4*>(h_sm + r * H_STRIDE + c4 * 4) = v;
        }
        __syncthreads();

        // Packed-pair GEMM: 2 rows x 4 cols, k in pairs via fma.rn.f32x2
        ull a00 = 0ull, a01 = 0ull, a02 = 0ull, a03 = 0ull;
        ull a10 = 0ull, a11 = 0ull, a12 = 0ull, a13 = 0ull;

#pragma unroll 4
        for (int k = 0; k < DH; k += 4) {
            ulonglong2 ha = *reinterpret_cast<const ulonglong2*>(hr0 + k);
            ulonglong2 hb = *reinterpret_cast<const ulonglong2*>(hr1 + k);
            ulonglong2 v0 = *reinterpret_cast<const ulonglong2*>(w0 + k);
            ulonglong2 v1 = *reinterpret_cast<const ulonglong2*>(w1 + k);
            ulonglong2 v2 = *reinterpret_cast<const ulonglong2*>(w2 + k);
            ulonglong2 v3 = *reinterpret_cast<const ulonglong2*>(w3 + k);
            a00 = fma2(ha.x, v0.x, a00); a00 = fma2(ha.y, v0.y, a00);
            a01 = fma2(ha.x, v1.x, a01); a01 = fma2(ha.y, v1.y, a01);
            a02 = fma2(ha.x, v2.x, a02); a02 = fma2(ha.y, v2.y, a02);
            a03 = fma2(ha.x, v3.x, a03); a03 = fma2(ha.y, v3.y, a03);
            a10 = fma2(hb.x, v0.x, a10); a10 = fma2(hb.y, v0.y, a10);
            a11 = fma2(hb.x, v1.x, a11); a11 = fma2(hb.y, v1.y, a11);
            a12 = fma2(hb.x, v2.x, a12); a12 = fma2(hb.y, v2.y, a12);
            a13 = fma2(hb.x, v3.x, a13); a13 = fma2(hb.y, v3.y, a13);
        }

        float4 o0 = make_float4(tanhf(sum2(a00) + x0.x + bias),
                                tanhf(sum2(a01) + x0.y + bias),
                                tanhf(sum2(a02) + x0.z + bias),
                                tanhf(sum2(a03) + x0.w + bias));
        float4 o1 = make_float4(tanhf(sum2(a10) + x1.x + bias),
                                tanhf(sum2(a11) + x1.y + bias),
                                tanhf(sum2(a12) + x1.z + bias),
                                tanhf(sum2(a13) + x1.w + bias));
        *reinterpret_cast<float4*>(hout + (size_t)(row0 + ty) * DH + col0 + tx * 4)      = o0;
        *reinterpret_cast<float4*>(hout + (size_t)(row0 + ty + 16) * DH + col0 + tx * 4) = o1;

        if (s < T_STEPS - 1) {
            __syncthreads();                          // all tile stores issued (two-stage release)
            if (tid == 0) st_release(&g_flag[s * NCTA + bid], 1u);
        }

        const float* tmp = hin; hin = hout; hout = const_cast<float*>(tmp);
    }
    // 512 steps (even): final h lives in g_h[0].
}

// -------------------- out = h_final @ W2 + b2 --------------------
__global__ void __launch_bounds__(128) out_kernel(const float* __restrict__ W2,
                                                  const float* __restrict__ b2p,
                                                  float* __restrict__ out) {
    __shared__ float hs[DH];
    const int b = blockIdx.x;
    const int o = threadIdx.x;
    for (int i = o; i < DH; i += 128) hs[i] = g_h[0][(size_t)b * DH + i];
    __syncthreads();
    float acc = b2p[0];
#pragma unroll 8
    for (int k = 0; k < DH; k++) acc += hs[k] * W2[(size_t)k * DOUT + o];
    out[(size_t)b * DOUT + o] = acc;
}

// -------------------- launch --------------------
extern "C" void kernel_launch(void* const* d_in, const int* in_sizes, int n_in,
                              void* d_out, int out_size) {
    const float* xs  = (const float*)d_in[0];
    const float* W1x = (const float*)d_in[1];
    const float* W1h = (const float*)d_in[2];
    const float* b1  = (const float*)d_in[3];
    const float* W2  = (const float*)d_in[4];
    const float* b2  = (const float*)d_in[5];
    float* out = (float*)d_out;

    (void)in_sizes; (void)n_in; (void)out_size;

    cudaFuncSetAttribute(xproj_kernel, cudaFuncAttributeMaxDynamicSharedMemorySize,
                         XPROJ_SMEM_FLOATS * (int)sizeof(float));
    cudaFuncSetAttribute(rec_kernel, cudaFuncAttributeMaxDynamicSharedMemorySize,
                         REC_SMEM_FLOATS * (int)sizeof(float));

    reset_kernel<<<256, 256>>>();
    xproj_kernel<<<dim3((T_STEPS * BATCH) / 64, DH / 64), 256,
                   XPROJ_SMEM_FLOATS * sizeof(float)>>>(xs, W1x);
    rec_kernel<<<NCTA, REC_THREADS, REC_SMEM_FLOATS * sizeof(float)>>>(W1h, b1);
    out_kernel<<<BATCH, 128>>>(W2, b2, out);
}